// round 1
// baseline (speedup 1.0000x reference)
#include <cuda_runtime.h>
#include <math.h>

#define T_TOK 8192
#define D_MOD 576
#define N_HEAD 9
#define HDIM 64
#define LAT 144
#define FF 1536
#define NE 7
#define SEQ 1024
#define ENT_CAP 16832   // 16384 entries + 7*64 padding headroom

// ---------------- scratch (static device allocations; no cudaMalloc) ----------
__device__ float g_h[T_TOK * D_MOD];
__device__ float g_qlat[T_TOK * LAT];
__device__ float g_kvlat[T_TOK * LAT];
__device__ float g_q[T_TOK * D_MOD];
__device__ float g_k[T_TOK * D_MOD];
__device__ float g_v[T_TOK * D_MOD];
__device__ float g_o[T_TOK * D_MOD];
__device__ float g_x2[T_TOK * D_MOD];
__device__ float g_h2[T_TOK * D_MOD];
__device__ float g_acts[T_TOK * FF];
__device__ float g_shared[T_TOK * D_MOD];
__device__ float g_w[T_TOK * 2];
__device__ int   g_top[T_TOK * 2];
__device__ int   g_cnt[NE];
__device__ int   g_offs[NE + 1];
__device__ int   g_cursor[NE];
__device__ int   g_entries[ENT_CAP];
__device__ float g_eact[ENT_CAP * FF];
__device__ float g_rout[T_TOK * 2 * D_MOD];

// ---------------- rmsnorm ----------------
__global__ void rmsnorm_kernel(const float* __restrict__ x,
                               const float* __restrict__ w,
                               float* __restrict__ out) {
    int t = blockIdx.x;
    int tid = threadIdx.x;                 // 192 threads, 3 cols each
    const float* xr = x + (size_t)t * D_MOD;
    float v0 = xr[tid], v1 = xr[tid + 192], v2 = xr[tid + 384];
    float ss = v0 * v0 + v1 * v1 + v2 * v2;
    for (int o = 16; o; o >>= 1) ss += __shfl_xor_sync(0xffffffffu, ss, o);
    __shared__ float red[8];
    int wid = tid >> 5, lane = tid & 31;
    if (lane == 0) red[wid] = ss;
    __syncthreads();
    if (tid == 0) {
        float s = 0.f;
        for (int i = 0; i < 6; ++i) s += red[i];
        red[0] = rsqrtf(s / (float)D_MOD + 1e-5f);
    }
    __syncthreads();
    float r = red[0];
    float* orow = out + (size_t)t * D_MOD;
    orow[tid]       = v0 * r * w[tid];
    orow[tid + 192] = v1 * r * w[tid + 192];
    orow[tid + 384] = v2 * r * w[tid + 384];
}

// ---------------- generic GEMM: C[M,N] = A[M,K] @ B[N,K]^T (+Res) ----------------
template <bool ADD>
__global__ void gemm64(const float* __restrict__ A, const float* __restrict__ Bw,
                       const float* __restrict__ Res, float* __restrict__ C,
                       int M, int N, int K) {
    __shared__ __align__(16) float As[16][68];
    __shared__ __align__(16) float Bs[16][68];
    int tid = threadIdx.x;
    int tx = tid & 15, ty = tid >> 4;
    int mBase = blockIdx.y * 64, nBase = blockIdx.x * 64;
    int lr = tid >> 2;
    int lk = (tid & 3) << 2;
    float acc[4][4] = {};
    for (int k0 = 0; k0 < K; k0 += 16) {
        float4 av = make_float4(0.f, 0.f, 0.f, 0.f);
        float4 bv = make_float4(0.f, 0.f, 0.f, 0.f);
        int am = mBase + lr;
        if (am < M) av = *(const float4*)(A + (size_t)am * K + k0 + lk);
        int bn = nBase + lr;
        if (bn < N) bv = *(const float4*)(Bw + (size_t)bn * K + k0 + lk);
        As[lk + 0][lr] = av.x; As[lk + 1][lr] = av.y; As[lk + 2][lr] = av.z; As[lk + 3][lr] = av.w;
        Bs[lk + 0][lr] = bv.x; Bs[lk + 1][lr] = bv.y; Bs[lk + 2][lr] = bv.z; Bs[lk + 3][lr] = bv.w;
        __syncthreads();
#pragma unroll
        for (int kk = 0; kk < 16; ++kk) {
            float4 a = *(const float4*)&As[kk][ty << 2];
            float4 b = *(const float4*)&Bs[kk][tx << 2];
            acc[0][0] += a.x * b.x; acc[0][1] += a.x * b.y; acc[0][2] += a.x * b.z; acc[0][3] += a.x * b.w;
            acc[1][0] += a.y * b.x; acc[1][1] += a.y * b.y; acc[1][2] += a.y * b.z; acc[1][3] += a.y * b.w;
            acc[2][0] += a.z * b.x; acc[2][1] += a.z * b.y; acc[2][2] += a.z * b.z; acc[2][3] += a.z * b.w;
            acc[3][0] += a.w * b.x; acc[3][1] += a.w * b.y; acc[3][2] += a.w * b.z; acc[3][3] += a.w * b.w;
        }
        __syncthreads();
    }
#pragma unroll
    for (int i = 0; i < 4; ++i) {
        int r = mBase + (ty << 2) + i;
        if (r >= M) break;
#pragma unroll
        for (int j = 0; j < 4; ++j) {
            int c = nBase + (tx << 2) + j;
            if (c < N) {
                float v = acc[i][j];
                if (ADD) v += Res[(size_t)r * N + c];
                C[(size_t)r * N + c] = v;
            }
        }
    }
}

// ---------------- fused SwiGLU gate+up GEMM (dense) ----------------
__global__ void gemm_swiglu(const float* __restrict__ A, const float* __restrict__ G,
                            const float* __restrict__ U, float* __restrict__ C,
                            int M, int N, int K) {
    __shared__ __align__(16) float As[16][68];
    __shared__ __align__(16) float Gs[16][68];
    __shared__ __align__(16) float Us[16][68];
    int tid = threadIdx.x;
    int tx = tid & 15, ty = tid >> 4;
    int mBase = blockIdx.y * 64, nBase = blockIdx.x * 64;
    int lr = tid >> 2;
    int lk = (tid & 3) << 2;
    float accg[4][4] = {}, accu[4][4] = {};
    for (int k0 = 0; k0 < K; k0 += 16) {
        float4 av = *(const float4*)(A + (size_t)(mBase + lr) * K + k0 + lk);
        float4 gv = *(const float4*)(G + (size_t)(nBase + lr) * K + k0 + lk);
        float4 uv = *(const float4*)(U + (size_t)(nBase + lr) * K + k0 + lk);
        As[lk + 0][lr] = av.x; As[lk + 1][lr] = av.y; As[lk + 2][lr] = av.z; As[lk + 3][lr] = av.w;
        Gs[lk + 0][lr] = gv.x; Gs[lk + 1][lr] = gv.y; Gs[lk + 2][lr] = gv.z; Gs[lk + 3][lr] = gv.w;
        Us[lk + 0][lr] = uv.x; Us[lk + 1][lr] = uv.y; Us[lk + 2][lr] = uv.z; Us[lk + 3][lr] = uv.w;
        __syncthreads();
#pragma unroll
        for (int kk = 0; kk < 16; ++kk) {
            float4 a = *(const float4*)&As[kk][ty << 2];
            float4 g = *(const float4*)&Gs[kk][tx << 2];
            float4 u = *(const float4*)&Us[kk][tx << 2];
            float aa[4] = {a.x, a.y, a.z, a.w};
            float gg[4] = {g.x, g.y, g.z, g.w};
            float uu[4] = {u.x, u.y, u.z, u.w};
#pragma unroll
            for (int i = 0; i < 4; ++i)
#pragma unroll
                for (int j = 0; j < 4; ++j) {
                    accg[i][j] += aa[i] * gg[j];
                    accu[i][j] += aa[i] * uu[j];
                }
        }
        __syncthreads();
    }
#pragma unroll
    for (int i = 0; i < 4; ++i) {
        int r = mBase + (ty << 2) + i;
#pragma unroll
        for (int j = 0; j < 4; ++j) {
            int c = nBase + (tx << 2) + j;
            float gv = accg[i][j];
            float silu = gv / (1.f + expf(-gv));
            C[(size_t)r * N + c] = silu * accu[i][j];
        }
    }
}

// ---------------- MoE fused SwiGLU (gathered rows) ----------------
__global__ void moe_swiglu(const float* __restrict__ h2, const float* __restrict__ rg,
                           const float* __restrict__ ru) {
    __shared__ int soff[8];
    __shared__ int stok[64];
    __shared__ __align__(16) float As[16][68];
    __shared__ __align__(16) float Gs[16][68];
    __shared__ __align__(16) float Us[16][68];
    int tid = threadIdx.x;
    if (tid < 8) soff[tid] = g_offs[tid];
    __syncthreads();
    int row0 = blockIdx.y * 64;
    if (row0 >= soff[7]) return;
    int e = 0;
    while (row0 >= soff[e + 1]) ++e;
    if (tid < 64) {
        int v = g_entries[row0 + tid];
        stok[tid] = (v >= 0) ? (v >> 1) : -1;
    }
    __syncthreads();
    const float* G = rg + (size_t)e * FF * D_MOD;
    const float* U = ru + (size_t)e * FF * D_MOD;
    int nBase = blockIdx.x * 64;
    int tx = tid & 15, ty = tid >> 4;
    int lr = tid >> 2;
    int lk = (tid & 3) << 2;
    int tok = stok[lr];
    float accg[4][4] = {}, accu[4][4] = {};
    for (int k0 = 0; k0 < D_MOD; k0 += 16) {
        float4 av = make_float4(0.f, 0.f, 0.f, 0.f);
        if (tok >= 0) av = *(const float4*)(h2 + (size_t)tok * D_MOD + k0 + lk);
        float4 gv = *(const float4*)(G + (size_t)(nBase + lr) * D_MOD + k0 + lk);
        float4 uv = *(const float4*)(U + (size_t)(nBase + lr) * D_MOD + k0 + lk);
        As[lk + 0][lr] = av.x; As[lk + 1][lr] = av.y; As[lk + 2][lr] = av.z; As[lk + 3][lr] = av.w;
        Gs[lk + 0][lr] = gv.x; Gs[lk + 1][lr] = gv.y; Gs[lk + 2][lr] = gv.z; Gs[lk + 3][lr] = gv.w;
        Us[lk + 0][lr] = uv.x; Us[lk + 1][lr] = uv.y; Us[lk + 2][lr] = uv.z; Us[lk + 3][lr] = uv.w;
        __syncthreads();
#pragma unroll
        for (int kk = 0; kk < 16; ++kk) {
            float4 a = *(const float4*)&As[kk][ty << 2];
            float4 g = *(const float4*)&Gs[kk][tx << 2];
            float4 u = *(const float4*)&Us[kk][tx << 2];
            float aa[4] = {a.x, a.y, a.z, a.w};
            float gg[4] = {g.x, g.y, g.z, g.w};
            float uu[4] = {u.x, u.y, u.z, u.w};
#pragma unroll
            for (int i = 0; i < 4; ++i)
#pragma unroll
                for (int j = 0; j < 4; ++j) {
                    accg[i][j] += aa[i] * gg[j];
                    accu[i][j] += aa[i] * uu[j];
                }
        }
        __syncthreads();
    }
#pragma unroll
    for (int i = 0; i < 4; ++i) {
        int rr = (ty << 2) + i;
        if (stok[rr] < 0) continue;
#pragma unroll
        for (int j = 0; j < 4; ++j) {
            int c = nBase + (tx << 2) + j;
            float gv = accg[i][j];
            float silu = gv / (1.f + expf(-gv));
            g_eact[(size_t)(row0 + rr) * FF + c] = silu * accu[i][j];
        }
    }
}

// ---------------- MoE down GEMM (gathered rows, scatter by entry) ----------------
__global__ void moe_down(const float* __restrict__ rd) {
    __shared__ int soff[8];
    __shared__ int sent[64];
    __shared__ __align__(16) float As[16][68];
    __shared__ __align__(16) float Bs[16][68];
    int tid = threadIdx.x;
    if (tid < 8) soff[tid] = g_offs[tid];
    __syncthreads();
    int row0 = blockIdx.y * 64;
    if (row0 >= soff[7]) return;
    int e = 0;
    while (row0 >= soff[e + 1]) ++e;
    if (tid < 64) sent[tid] = g_entries[row0 + tid];
    __syncthreads();
    const float* B = rd + (size_t)e * D_MOD * FF;
    int nBase = blockIdx.x * 64;
    int tx = tid & 15, ty = tid >> 4;
    int lr = tid >> 2;
    int lk = (tid & 3) << 2;
    float acc[4][4] = {};
    for (int k0 = 0; k0 < FF; k0 += 16) {
        float4 av = *(const float4*)(g_eact + (size_t)(row0 + lr) * FF + k0 + lk);
        float4 bv = *(const float4*)(B + (size_t)(nBase + lr) * FF + k0 + lk);
        As[lk + 0][lr] = av.x; As[lk + 1][lr] = av.y; As[lk + 2][lr] = av.z; As[lk + 3][lr] = av.w;
        Bs[lk + 0][lr] = bv.x; Bs[lk + 1][lr] = bv.y; Bs[lk + 2][lr] = bv.z; Bs[lk + 3][lr] = bv.w;
        __syncthreads();
#pragma unroll
        for (int kk = 0; kk < 16; ++kk) {
            float4 a = *(const float4*)&As[kk][ty << 2];
            float4 b = *(const float4*)&Bs[kk][tx << 2];
            acc[0][0] += a.x * b.x; acc[0][1] += a.x * b.y; acc[0][2] += a.x * b.z; acc[0][3] += a.x * b.w;
            acc[1][0] += a.y * b.x; acc[1][1] += a.y * b.y; acc[1][2] += a.y * b.z; acc[1][3] += a.y * b.w;
            acc[2][0] += a.z * b.x; acc[2][1] += a.z * b.y; acc[2][2] += a.z * b.z; acc[2][3] += a.z * b.w;
            acc[3][0] += a.w * b.x; acc[3][1] += a.w * b.y; acc[3][2] += a.w * b.z; acc[3][3] += a.w * b.w;
        }
        __syncthreads();
    }
#pragma unroll
    for (int i = 0; i < 4; ++i) {
        int v = sent[(ty << 2) + i];
        if (v < 0) continue;
#pragma unroll
        for (int j = 0; j < 4; ++j) {
            int c = nBase + (tx << 2) + j;
            g_rout[(size_t)v * D_MOD + c] = acc[i][j];
        }
    }
}

// ---------------- RoPE (in-place on q,k) ----------------
__global__ void rope_kernel(float* __restrict__ q, float* __restrict__ k) {
    int t = blockIdx.x;
    int tid = threadIdx.x;          // 288 = 9 heads * 32 pairs
    int h = tid >> 5, i = tid & 31;
    int pos = t & (SEQ - 1);
    float inv = __expf(-(float)i * 0.28782313662425572f);  // ln(10000)/32
    float f = (float)pos * inv;
    float sv, cv;
    sincosf(f, &sv, &cv);
    size_t base = (size_t)t * D_MOD + h * HDIM + i;
    float q1 = q[base], q2 = q[base + 32];
    q[base]      = q1 * cv - q2 * sv;
    q[base + 32] = q2 * cv + q1 * sv;
    float k1 = k[base], k2 = k[base + 32];
    k[base]      = k1 * cv - k2 * sv;
    k[base + 32] = k2 * cv + k1 * sv;
}

// ---------------- flash attention (fp32, causal, online softmax) ----------------
__global__ void attn_kernel(const float* __restrict__ Q, const float* __restrict__ K,
                            const float* __restrict__ V, float* __restrict__ O) {
    extern __shared__ float sm[];
    float* qs = sm;            // 64*64
    float* ks = sm + 4096;     // 64*64
    float* vs = sm + 8192;     // 64*64
    float* sc = sm + 12288;    // 64*65
    int qt = blockIdx.x;
    int bh = blockIdx.y;
    int b = bh / N_HEAD, h = bh % N_HEAD;
    int tid = threadIdx.x;     // 256
    int r = tid >> 2, j = tid & 3;
    size_t head_off = (size_t)h * HDIM;

    for (int i = tid; i < 4096; i += 256) {
        int rr = i >> 6, d = i & 63;
        qs[i] = Q[((size_t)(b * SEQ + qt * 64 + rr)) * D_MOD + head_off + d];
    }

    int qpos = qt * 64 + r;
    float m_i = -1e30f, l_i = 0.f;
    float acc[16];
#pragma unroll
    for (int d = 0; d < 16; ++d) acc[d] = 0.f;

    for (int kt = 0; kt <= qt; ++kt) {
        __syncthreads();  // protect ks/vs/sc from previous iteration readers
        for (int i = tid; i < 4096; i += 256) {
            int rr = i >> 6, d = i & 63;
            size_t gofs = ((size_t)(b * SEQ + kt * 64 + rr)) * D_MOD + head_off + d;
            ks[i] = K[gofs];
            vs[i] = V[gofs];
        }
        __syncthreads();

        float s[16];
        const float* qrow = qs + r * 64;
#pragma unroll 4
        for (int cc = 0; cc < 16; ++cc) {
            int c = j * 16 + cc;
            const float* krow = ks + c * 64;
            float dot = 0.f;
#pragma unroll
            for (int kk = 0; kk < 64; kk += 4) {
                float4 qa = *(const float4*)(qrow + kk);
                float4 ka = *(const float4*)(krow + kk);
                dot += qa.x * ka.x + qa.y * ka.y + qa.z * ka.z + qa.w * ka.w;
            }
            int kpos = kt * 64 + c;
            s[cc] = (kpos <= qpos) ? dot * 0.125f : -1e30f;
        }
        float mloc = s[0];
#pragma unroll
        for (int cc = 1; cc < 16; ++cc) mloc = fmaxf(mloc, s[cc]);
        mloc = fmaxf(mloc, __shfl_xor_sync(0xffffffffu, mloc, 1));
        mloc = fmaxf(mloc, __shfl_xor_sync(0xffffffffu, mloc, 2));
        float m_new = fmaxf(m_i, mloc);
        float scale = __expf(m_i - m_new);
        float ps = 0.f;
#pragma unroll
        for (int cc = 0; cc < 16; ++cc) {
            float p = __expf(s[cc] - m_new);
            ps += p;
            sc[r * 65 + j * 16 + cc] = p;
        }
        ps += __shfl_xor_sync(0xffffffffu, ps, 1);
        ps += __shfl_xor_sync(0xffffffffu, ps, 2);
        l_i = l_i * scale + ps;
        m_i = m_new;
#pragma unroll
        for (int d = 0; d < 16; ++d) acc[d] *= scale;
        __syncthreads();
#pragma unroll 4
        for (int c = 0; c < 64; ++c) {
            float p = sc[r * 65 + c];
            const float4* vrow = (const float4*)(vs + c * 64 + j * 16);
#pragma unroll
            for (int d4 = 0; d4 < 4; ++d4) {
                float4 vv = vrow[d4];
                acc[d4 * 4 + 0] += p * vv.x;
                acc[d4 * 4 + 1] += p * vv.y;
                acc[d4 * 4 + 2] += p * vv.z;
                acc[d4 * 4 + 3] += p * vv.w;
            }
        }
    }
    float invl = 1.f / l_i;
    float* orow = O + ((size_t)(b * SEQ + qpos)) * D_MOD + head_off + j * 16;
#pragma unroll
    for (int d = 0; d < 16; ++d) orow[d] = acc[d] * invl;
}

// ---------------- router + gather bookkeeping ----------------
__global__ void zero_cnt_kernel() {
    if (threadIdx.x < NE) g_cnt[threadIdx.x] = 0;
}

__global__ void router_kernel(const float* __restrict__ h2, const float* __restrict__ Wr,
                              const float* __restrict__ rb) {
    int t = blockIdx.x;
    int w = threadIdx.x >> 5, lane = threadIdx.x & 31;
    __shared__ float sl[NE];
    if (w < NE) {
        const float* hr = h2 + (size_t)t * D_MOD;
        const float* wr = Wr + w * D_MOD;
        float s = 0.f;
        for (int c = lane; c < D_MOD; c += 32) s += hr[c] * wr[c];
        for (int o = 16; o; o >>= 1) s += __shfl_xor_sync(0xffffffffu, s, o);
        if (lane == 0) sl[w] = s + rb[w];
    }
    __syncthreads();
    if (threadIdx.x == 0) {
        float p[NE];
#pragma unroll
        for (int e2 = 0; e2 < NE; ++e2) p[e2] = 1.f / (1.f + expf(-sl[e2]));
        int i0 = 0;
#pragma unroll
        for (int e2 = 1; e2 < NE; ++e2) if (p[e2] > p[i0]) i0 = e2;
        int i1 = -1;
#pragma unroll
        for (int e2 = 0; e2 < NE; ++e2) {
            if (e2 == i0) continue;
            if (i1 < 0 || p[e2] > p[i1]) i1 = e2;
        }
        float sum = p[i0] + p[i1];
        g_top[t * 2] = i0; g_top[t * 2 + 1] = i1;
        g_w[t * 2] = p[i0] / sum; g_w[t * 2 + 1] = p[i1] / sum;
        atomicAdd(&g_cnt[i0], 1);
        atomicAdd(&g_cnt[i1], 1);
    }
}

__global__ void offsets_kernel() {
    int off = 0;
    for (int e = 0; e < NE; ++e) {
        g_offs[e] = off;
        g_cursor[e] = off;
        int c = g_cnt[e];
        int padded = ((c + 63) >> 6) << 6;
        for (int i = c; i < padded; ++i) g_entries[off + i] = -1;
        off += padded;
    }
    g_offs[NE] = off;
}

__global__ void scatter_kernel() {
    int t = blockIdx.x * blockDim.x + threadIdx.x;
    if (t >= T_TOK) return;
#pragma unroll
    for (int slot = 0; slot < 2; ++slot) {
        int e = g_top[t * 2 + slot];
        int pos = atomicAdd(&g_cursor[e], 1);
        g_entries[pos] = t * 2 + slot;
    }
}

// ---------------- final combine ----------------
__global__ void combine_kernel(float* __restrict__ out) {
    int t = blockIdx.x;
    int tid = threadIdx.x;  // 192
    float w0 = g_w[t * 2], w1 = g_w[t * 2 + 1];
    size_t b0 = (size_t)(t * 2) * D_MOD;
    size_t b1 = (size_t)(t * 2 + 1) * D_MOD;
    size_t bt = (size_t)t * D_MOD;
#pragma unroll
    for (int u = 0; u < 3; ++u) {
        int c = tid + u * 192;
        out[bt + c] = g_x2[bt + c] + g_shared[bt + c]
                    + w0 * g_rout[b0 + c] + w1 * g_rout[b1 + c];
    }
}

// ---------------- launcher ----------------
extern "C" void kernel_launch(void* const* d_in, const int* in_sizes, int n_in,
                              void* d_out, int out_size) {
    const float* x    = (const float*)d_in[0];
    const float* ln1w = (const float*)d_in[1];
    const float* ln2w = (const float*)d_in[2];
    const float* Wqd  = (const float*)d_in[3];
    const float* Wkvd = (const float*)d_in[4];
    const float* Wqu  = (const float*)d_in[5];
    const float* Wku  = (const float*)d_in[6];
    const float* Wvu  = (const float*)d_in[7];
    const float* Wo   = (const float*)d_in[8];
    const float* sg   = (const float*)d_in[9];
    const float* su   = (const float*)d_in[10];
    const float* sd   = (const float*)d_in[11];
    const float* rg   = (const float*)d_in[12];
    const float* ru   = (const float*)d_in[13];
    const float* rd   = (const float*)d_in[14];
    const float* Wr   = (const float*)d_in[15];
    const float* rb   = (const float*)d_in[16];
    float* out = (float*)d_out;

    float *ph, *pqlat, *pkvlat, *pq, *pk, *pv, *po, *px2, *ph2, *pacts, *pshared;
    cudaGetSymbolAddress((void**)&ph, g_h);
    cudaGetSymbolAddress((void**)&pqlat, g_qlat);
    cudaGetSymbolAddress((void**)&pkvlat, g_kvlat);
    cudaGetSymbolAddress((void**)&pq, g_q);
    cudaGetSymbolAddress((void**)&pk, g_k);
    cudaGetSymbolAddress((void**)&pv, g_v);
    cudaGetSymbolAddress((void**)&po, g_o);
    cudaGetSymbolAddress((void**)&px2, g_x2);
    cudaGetSymbolAddress((void**)&ph2, g_h2);
    cudaGetSymbolAddress((void**)&pacts, g_acts);
    cudaGetSymbolAddress((void**)&pshared, g_shared);

    const int MB = T_TOK / 64;  // 128 row blocks

    zero_cnt_kernel<<<1, 32>>>();
    rmsnorm_kernel<<<T_TOK, 192>>>(x, ln1w, ph);

    gemm64<false><<<dim3(3, MB), 256>>>(ph, Wqd, nullptr, pqlat, T_TOK, LAT, D_MOD);
    gemm64<false><<<dim3(3, MB), 256>>>(ph, Wkvd, nullptr, pkvlat, T_TOK, LAT, D_MOD);
    gemm64<false><<<dim3(9, MB), 256>>>(pqlat, Wqu, nullptr, pq, T_TOK, D_MOD, LAT);
    gemm64<false><<<dim3(9, MB), 256>>>(pkvlat, Wku, nullptr, pk, T_TOK, D_MOD, LAT);
    gemm64<false><<<dim3(9, MB), 256>>>(pkvlat, Wvu, nullptr, pv, T_TOK, D_MOD, LAT);

    rope_kernel<<<T_TOK, 288>>>(pq, pk);

    const int ATTN_SMEM = (3 * 4096 + 64 * 65) * 4;  // 65792 B
    cudaFuncSetAttribute(attn_kernel, cudaFuncAttributeMaxDynamicSharedMemorySize, ATTN_SMEM);
    attn_kernel<<<dim3(SEQ / 64, 8 * N_HEAD), 256, ATTN_SMEM>>>(pq, pk, pv, po);

    gemm64<true><<<dim3(9, MB), 256>>>(po, Wo, x, px2, T_TOK, D_MOD, D_MOD);
    rmsnorm_kernel<<<T_TOK, 192>>>(px2, ln2w, ph2);

    gemm_swiglu<<<dim3(FF / 64, MB), 256>>>(ph2, sg, su, pacts, T_TOK, FF, D_MOD);
    gemm64<false><<<dim3(9, MB), 256>>>(pacts, sd, nullptr, pshared, T_TOK, D_MOD, FF);

    router_kernel<<<T_TOK, 256>>>(ph2, Wr, rb);
    offsets_kernel<<<1, 1>>>();
    scatter_kernel<<<T_TOK / 256, 256>>>();

    moe_swiglu<<<dim3(FF / 64, ENT_CAP / 64), 256>>>(ph2, rg, ru);
    moe_down<<<dim3(9, ENT_CAP / 64), 256>>>(rd);

    combine_kernel<<<T_TOK, 192>>>(out);
}